// round 4
// baseline (speedup 1.0000x reference)
#include <cuda_runtime.h>
#include <cuda_bf16.h>
#include <math_constants.h>

// R4: resubmission of R3 kernel (R3 failed on infra, never ran).

#define N_NODES 100000
#define N_EDGES 3200000
#define C_IN    128
#define HID     64
#define COUT    40

// ---------------- scratch (device globals; no allocation allowed) ----------
__device__ __align__(16) float g_dinv[N_NODES];          // deg, then deg^{-1/2}
__device__ __align__(16) float g_h1  [N_NODES * HID];    // x @ W1
__device__ __align__(16) float g_agg1[N_NODES * HID];    // scatter target L1
__device__ __align__(16) float g_h2  [N_NODES * COUT];   // relu(agg1+b1) @ W2
__device__ __align__(16) float g_agg2[N_NODES * COUT];   // scatter target L2
__device__ int g_idx64;                                   // 1 if edge_index is int64

// ---------------- edge-index accessor (dtype-agnostic) ---------------------
__device__ __forceinline__ void load_edge(const void* ei, int e, int E,
                                          int& src, int& dst) {
    if (g_idx64) {
        const long long* p = (const long long*)ei;
        src = (int)__ldg(&p[e]);
        dst = (int)__ldg(&p[E + e]);
    } else {
        const int* p = (const int*)ei;
        src = __ldg(&p[e]);
        dst = __ldg(&p[E + e]);
    }
}

// ---------------- detect edge dtype: int64 => odd 32-bit words all zero ----
__global__ void k_detect(const int* __restrict__ ei32) {
    // single thread: sample 64 odd words; node ids < 2^31 so int64 high words are 0
    int all_zero = 1;
    for (int i = 0; i < 64; i++) {
        if (ei32[2 * i + 1] != 0) { all_zero = 0; break; }
    }
    g_idx64 = all_zero;
}

// ---------------- zero scratch (agg buffers + deg) -------------------------
__global__ void k_zero() {
    int i = blockIdx.x * blockDim.x + threadIdx.x;
    int stride = gridDim.x * blockDim.x;
    float4 z = make_float4(0.f, 0.f, 0.f, 0.f);
    for (int j = i; j < N_NODES / 4; j += stride)         ((float4*)g_dinv)[j] = z;
    for (int j = i; j < N_NODES * HID / 4; j += stride)   ((float4*)g_agg1)[j] = z;
    for (int j = i; j < N_NODES * COUT / 4; j += stride)  ((float4*)g_agg2)[j] = z;
}

// ---------------- degree (in-degree at dst) --------------------------------
__global__ void k_deg(const void* __restrict__ ei, int E) {
    int e = blockIdx.x * blockDim.x + threadIdx.x;
    if (e < E) {
        int src, dst;
        load_edge(ei, e, E, src, dst);
        atomicAdd(&g_dinv[dst], 1.0f);
    }
}

__global__ void k_dinv(int N) {
    int i = blockIdx.x * blockDim.x + threadIdx.x;
    if (i < N) {
        float d = g_dinv[i];
        g_dinv[i] = (d > 0.f) ? rsqrtf(d) : 0.f;
    }
}

// ---------------- GEMM1: h1 = x @ W1  (one warp per row) -------------------
__global__ void k_gemm1(const float* __restrict__ x, const float* __restrict__ W1, int N) {
    __shared__ float2 Ws[C_IN * 32];   // W1 as float2 pairs: [k][colpair]
    int tid = threadIdx.x;
    const float2* W2p = (const float2*)W1;  // row-major [128,64] -> adjacent cols pair
    for (int i = tid; i < C_IN * 32; i += blockDim.x) Ws[i] = W2p[i];
    __syncthreads();

    int row  = (blockIdx.x * blockDim.x + tid) >> 5;
    int lane = tid & 31;
    if (row >= N) return;

    float xr[4];
#pragma unroll
    for (int j = 0; j < 4; j++) xr[j] = x[row * C_IN + j * 32 + lane];

    float2 acc = make_float2(0.f, 0.f);
#pragma unroll
    for (int k = 0; k < C_IN; k++) {
        float xv = __shfl_sync(0xffffffffu, xr[k >> 5], k & 31);
        float2 w = Ws[k * 32 + lane];
        acc.x += xv * w.x;
        acc.y += xv * w.y;
    }
    ((float2*)g_h1)[row * 32 + lane] = acc;
}

// ---------------- edge scatter layer 1: 16 lanes per edge ------------------
__global__ void k_scat1(const void* __restrict__ ei, int E) {
    int idx = blockIdx.x * blockDim.x + threadIdx.x;
    int e = idx >> 4;
    int sub = idx & 15;
    if (e >= E) return;
    int src, dst;
    load_edge(ei, e, E, src, dst);
    float norm = __ldg(&g_dinv[src]) * __ldg(&g_dinv[dst]);
    float4 v = *((const float4*)(g_h1 + src * HID + sub * 4));
    float4* p = (float4*)(g_agg1 + dst * HID + sub * 4);
    asm volatile("red.global.add.v4.f32 [%0], {%1,%2,%3,%4};"
                 :: "l"(p), "f"(v.x * norm), "f"(v.y * norm),
                    "f"(v.z * norm), "f"(v.w * norm) : "memory");
}

// ---------------- GEMM2 fused relu+bias: h2 = relu(agg1+b1) @ W2 -----------
__global__ void k_gemm2(const float* __restrict__ W2, const float* __restrict__ b1, int N) {
    __shared__ float Ws[HID * COUT + 64];   // padded: acc1 path reads up to +63
    __shared__ float b1s[HID];
    int tid = threadIdx.x;
    for (int i = tid; i < HID * COUT + 64; i += blockDim.x)
        Ws[i] = (i < HID * COUT) ? W2[i] : 0.f;
    if (tid < HID) b1s[tid] = b1[tid];
    __syncthreads();

    int row  = (blockIdx.x * blockDim.x + tid) >> 5;
    int lane = tid & 31;
    if (row >= N) return;

    float a0 = fmaxf(g_agg1[row * HID + lane]      + b1s[lane],      0.f);
    float a1 = fmaxf(g_agg1[row * HID + 32 + lane] + b1s[32 + lane], 0.f);

    float acc0 = 0.f, acc1 = 0.f;
#pragma unroll
    for (int k = 0; k < 32; k++) {
        float xv = __shfl_sync(0xffffffffu, a0, k);
        acc0 += xv * Ws[k * COUT + lane];
        acc1 += xv * Ws[k * COUT + lane + 32];
    }
#pragma unroll
    for (int k = 0; k < 32; k++) {
        float xv = __shfl_sync(0xffffffffu, a1, k);
        acc0 += xv * Ws[(k + 32) * COUT + lane];
        acc1 += xv * Ws[(k + 32) * COUT + lane + 32];
    }
    g_h2[row * COUT + lane] = acc0;                    // cols 0..31
    if (lane < COUT - 32) g_h2[row * COUT + 32 + lane] = acc1;  // cols 32..39
}

// ---------------- edge scatter layer 2: 10 lanes (of 32, 3 edges/warp) -----
__global__ void k_scat2(const void* __restrict__ ei, int E) {
    int idx = blockIdx.x * blockDim.x + threadIdx.x;
    int w = idx >> 5;
    int lane = idx & 31;
    int i = lane / 10;           // 0..2 active; lanes 30,31 idle (i==3)
    int c = lane - i * 10;       // chunk 0..9 (float4 -> 40 floats)
    if (i >= 3) return;
    long long e64 = (long long)w * 3 + i;
    if (e64 >= E) return;
    int e = (int)e64;
    int src, dst;
    load_edge(ei, e, E, src, dst);
    float norm = __ldg(&g_dinv[src]) * __ldg(&g_dinv[dst]);
    float4 v = *((const float4*)(g_h2 + src * COUT + c * 4));
    float4* p = (float4*)(g_agg2 + dst * COUT + c * 4);
    asm volatile("red.global.add.v4.f32 [%0], {%1,%2,%3,%4};"
                 :: "l"(p), "f"(v.x * norm), "f"(v.y * norm),
                    "f"(v.z * norm), "f"(v.w * norm) : "memory");
}

// ---------------- finalize: bias + log_softmax (one warp per node) ---------
__global__ void k_final(const float* __restrict__ b2, float* __restrict__ out, int N) {
    int tid = blockIdx.x * blockDim.x + threadIdx.x;
    int row = tid >> 5;
    int lane = tid & 31;
    if (row >= N) return;

    float v0 = g_agg2[row * COUT + lane] + b2[lane];           // lanes 0..31 valid
    bool has1 = lane < (COUT - 32);                             // lanes 0..7
    float v1 = has1 ? (g_agg2[row * COUT + 32 + lane] + b2[32 + lane]) : -CUDART_INF_F;

    float m = fmaxf(v0, v1);
#pragma unroll
    for (int o = 16; o; o >>= 1) m = fmaxf(m, __shfl_xor_sync(0xffffffffu, m, o));

    float s = __expf(v0 - m) + (has1 ? __expf(v1 - m) : 0.f);
#pragma unroll
    for (int o = 16; o; o >>= 1) s += __shfl_xor_sync(0xffffffffu, s, o);

    float lg = m + logf(s);
    out[row * COUT + lane] = v0 - lg;
    if (has1) out[row * COUT + 32 + lane] = v1 - lg;
}

// ---------------- launch ----------------------------------------------------
extern "C" void kernel_launch(void* const* d_in, const int* in_sizes, int n_in,
                              void* d_out, int out_size) {
    const float* x  = (const float*)d_in[0];
    const void*  ei = d_in[1];
    const float* W1 = (const float*)d_in[2];
    const float* b1 = (const float*)d_in[3];
    const float* W2 = (const float*)d_in[4];
    const float* b2 = (const float*)d_in[5];
    float* out = (float*)d_out;

    int N = in_sizes[0] / C_IN;     // 100000
    int E = in_sizes[1] / 2;        // 3200000

    k_detect<<<1, 1>>>((const int*)ei);
    k_zero<<<2048, 256>>>();
    k_deg<<<(E + 255) / 256, 256>>>(ei, E);
    k_dinv<<<(N + 255) / 256, 256>>>(N);
    k_gemm1<<<(N * 32 + 255) / 256, 256>>>(x, W1, N);
    {
        long long threads = (long long)E * 16;
        k_scat1<<<(int)((threads + 255) / 256), 256>>>(ei, E);
    }
    k_gemm2<<<(N * 32 + 255) / 256, 256>>>(W2, b1, N);
    {
        long long warps = ((long long)E + 2) / 3;
        long long threads = warps * 32;
        k_scat2<<<(int)((threads + 255) / 256), 256>>>(ei, E);
    }
    k_final<<<(N * 32 + 255) / 256, 256>>>(b2, out, N);
}

// round 5
// speedup vs baseline: 1.3539x; 1.3539x over previous
#include <cuda_runtime.h>
#include <cuda_bf16.h>
#include <math_constants.h>

// R5: CSR-binned gather aggregation (no float atomics), fused epilogues.

#define N_NODES 100000
#define N_EDGES 3200000
#define C_IN    128
#define HID     64
#define COUT    40
#define SCAN_BLK 1024

// ---------------- scratch (device globals; no allocation allowed) ----------
__device__ __align__(16) float g_dinv[N_NODES];
__device__ __align__(16) int   g_deg [N_NODES];
__device__ __align__(16) int   g_rowstart[N_NODES];
__device__ __align__(16) int   g_cursor  [N_NODES];
__device__ __align__(16) int   g_bsum[128];
__device__ __align__(16) int2  g_edge[N_EDGES];          // {src, norm bits} dst-sorted
__device__ __align__(16) float g_h1  [N_NODES * HID];    // x @ W1
__device__ __align__(16) float g_h2  [N_NODES * COUT];   // layer-1 output
__device__ int g_idx64;

// ---------------- edge-index accessor (dtype-agnostic) ---------------------
__device__ __forceinline__ void load_edge(const void* ei, int e, int E,
                                          int& src, int& dst) {
    if (g_idx64) {
        const long long* p = (const long long*)ei;
        src = (int)__ldg(&p[e]);
        dst = (int)__ldg(&p[E + e]);
    } else {
        const int* p = (const int*)ei;
        src = __ldg(&p[e]);
        dst = __ldg(&p[E + e]);
    }
}

__global__ void k_detect(const int* __restrict__ ei32) {
    int all_zero = 1;
    for (int i = 0; i < 64; i++)
        if (ei32[2 * i + 1] != 0) { all_zero = 0; break; }
    g_idx64 = all_zero;
}

// ---------------- zero degree ----------------------------------------------
__global__ void k_zerodeg(int N) {
    int i = blockIdx.x * blockDim.x + threadIdx.x;
    if (i < N) g_deg[i] = 0;
}

// ---------------- histogram of dst (= in-degree) ---------------------------
__global__ void k_hist(const void* __restrict__ ei, int E) {
    int e = blockIdx.x * blockDim.x + threadIdx.x;
    if (e < E) {
        int src, dst;
        load_edge(ei, e, E, src, dst);
        atomicAdd(&g_deg[dst], 1);
    }
}

// ---------------- scan phase A: per-block exclusive scan -------------------
__global__ void k_scanA(int N) {
    __shared__ int s[SCAN_BLK];
    int tid = threadIdx.x;
    int i = blockIdx.x * SCAN_BLK + tid;
    int own = (i < N) ? g_deg[i] : 0;
    s[tid] = own;
    __syncthreads();
#pragma unroll
    for (int off = 1; off < SCAN_BLK; off <<= 1) {
        int v = (tid >= off) ? s[tid - off] : 0;
        __syncthreads();
        s[tid] += v;
        __syncthreads();
    }
    if (i < N) g_rowstart[i] = s[tid] - own;
    if (tid == SCAN_BLK - 1) g_bsum[blockIdx.x] = s[tid];
}

// ---------------- scan phase B: scan block totals (1 block) ----------------
__global__ void k_scanB(int nblk) {
    __shared__ int s[128];
    int tid = threadIdx.x;
    int own = (tid < nblk) ? g_bsum[tid] : 0;
    s[tid] = own;
    __syncthreads();
#pragma unroll
    for (int off = 1; off < 128; off <<= 1) {
        int v = (tid >= off) ? s[tid - off] : 0;
        __syncthreads();
        s[tid] += v;
        __syncthreads();
    }
    if (tid < nblk) g_bsum[tid] = s[tid] - own;
}

// ---------------- scan phase C: add offsets, init cursor, dinv -------------
__global__ void k_scanC(int N) {
    int i = blockIdx.x * blockDim.x + threadIdx.x;
    if (i < N) {
        int rs = g_rowstart[i] + g_bsum[i / SCAN_BLK];
        g_rowstart[i] = rs;
        g_cursor[i] = rs;
        int d = g_deg[i];
        g_dinv[i] = (d > 0) ? rsqrtf((float)d) : 0.f;
    }
}

// ---------------- bucket edges by dst (sorted (src, norm) list) ------------
__global__ void k_bucket(const void* __restrict__ ei, int E) {
    int e = blockIdx.x * blockDim.x + threadIdx.x;
    if (e < E) {
        int src, dst;
        load_edge(ei, e, E, src, dst);
        float norm = __ldg(&g_dinv[src]) * __ldg(&g_dinv[dst]);
        int pos = atomicAdd(&g_cursor[dst], 1);
        g_edge[pos] = make_int2(src, __float_as_int(norm));
    }
}

// ---------------- GEMM1: h1 = x @ W1  (one warp per row) -------------------
__global__ void k_gemm1(const float* __restrict__ x, const float* __restrict__ W1, int N) {
    __shared__ float2 Ws[C_IN * 32];
    int tid = threadIdx.x;
    const float2* W2p = (const float2*)W1;
    for (int i = tid; i < C_IN * 32; i += blockDim.x) Ws[i] = W2p[i];
    __syncthreads();

    int row  = (blockIdx.x * blockDim.x + tid) >> 5;
    int lane = tid & 31;
    if (row >= N) return;

    float xr[4];
#pragma unroll
    for (int j = 0; j < 4; j++) xr[j] = x[row * C_IN + j * 32 + lane];

    float2 acc = make_float2(0.f, 0.f);
#pragma unroll
    for (int k = 0; k < C_IN; k++) {
        float xv = __shfl_sync(0xffffffffu, xr[k >> 5], k & 31);
        float2 w = Ws[k * 32 + lane];
        acc.x += xv * w.x;
        acc.y += xv * w.y;
    }
    ((float2*)g_h1)[row * 32 + lane] = acc;
}

// ---------------- layer1 aggregate + bias + relu + GEMM2 (warp per node) ---
__global__ void k_agg1g2(const float* __restrict__ W2, const float* __restrict__ b1, int N) {
    __shared__ float Ws[HID * COUT + 64];   // padded: acc1 path reads up to +63
    __shared__ float b1s[HID];
    int tid = threadIdx.x;
    for (int i = tid; i < HID * COUT + 64; i += blockDim.x)
        Ws[i] = (i < HID * COUT) ? W2[i] : 0.f;
    if (tid < HID) b1s[tid] = b1[tid];
    __syncthreads();

    int row  = (blockIdx.x * blockDim.x + tid) >> 5;
    int lane = tid & 31;
    if (row >= N) return;

    int start = g_rowstart[row];
    int cnt   = g_deg[row];

    float2 acc = make_float2(0.f, 0.f);
    for (int base = 0; base < cnt; base += 32) {
        int j = base + lane;
        int2 ed = (j < cnt) ? g_edge[start + j] : make_int2(0, 0);
        int m = min(32, cnt - base);
        for (int t = 0; t < m; t++) {
            int   s   = __shfl_sync(0xffffffffu, ed.x, t);
            float nrm = __int_as_float(__shfl_sync(0xffffffffu, ed.y, t));
            float2 v = ((const float2*)g_h1)[s * 32 + lane];
            acc.x += v.x * nrm;
            acc.y += v.y * nrm;
        }
    }

    // relu(agg + b1); lane holds cols 2*lane, 2*lane+1
    float c0 = fmaxf(acc.x + b1s[2 * lane],     0.f);
    float c1 = fmaxf(acc.y + b1s[2 * lane + 1], 0.f);

    float o0 = 0.f, o1 = 0.f;
#pragma unroll
    for (int k = 0; k < HID; k++) {
        float xv = __shfl_sync(0xffffffffu, (k & 1) ? c1 : c0, k >> 1);
        o0 += xv * Ws[k * COUT + lane];
        o1 += xv * Ws[k * COUT + lane + 32];
    }
    g_h2[row * COUT + lane] = o0;
    if (lane < COUT - 32) g_h2[row * COUT + 32 + lane] = o1;
}

// ---------------- layer2 aggregate + bias + log_softmax (warp per node) ----
__global__ void k_agg2fin(const float* __restrict__ b2, float* __restrict__ out, int N) {
    int tid = blockIdx.x * blockDim.x + threadIdx.x;
    int row = tid >> 5;
    int lane = tid & 31;
    if (row >= N) return;

    int start = g_rowstart[row];
    int cnt   = g_deg[row];
    bool has1 = lane < (COUT - 32);

    float a0 = 0.f, a1 = 0.f;
    for (int base = 0; base < cnt; base += 32) {
        int j = base + lane;
        int2 ed = (j < cnt) ? g_edge[start + j] : make_int2(0, 0);
        int m = min(32, cnt - base);
        for (int t = 0; t < m; t++) {
            int   s   = __shfl_sync(0xffffffffu, ed.x, t);
            float nrm = __int_as_float(__shfl_sync(0xffffffffu, ed.y, t));
            float v0 = g_h2[s * COUT + lane];
            a0 += v0 * nrm;
            if (has1) a1 += g_h2[s * COUT + 32 + lane] * nrm;
        }
    }

    float v0 = a0 + b2[lane];
    float v1 = has1 ? (a1 + b2[32 + lane]) : -CUDART_INF_F;

    float mx = fmaxf(v0, v1);
#pragma unroll
    for (int o = 16; o; o >>= 1) mx = fmaxf(mx, __shfl_xor_sync(0xffffffffu, mx, o));

    float sm = __expf(v0 - mx) + (has1 ? __expf(v1 - mx) : 0.f);
#pragma unroll
    for (int o = 16; o; o >>= 1) sm += __shfl_xor_sync(0xffffffffu, sm, o);

    float lg = mx + logf(sm);
    out[row * COUT + lane] = v0 - lg;
    if (has1) out[row * COUT + 32 + lane] = v1 - lg;
}

// ---------------- launch ----------------------------------------------------
extern "C" void kernel_launch(void* const* d_in, const int* in_sizes, int n_in,
                              void* d_out, int out_size) {
    const float* x  = (const float*)d_in[0];
    const void*  ei = d_in[1];
    const float* W1 = (const float*)d_in[2];
    const float* b1 = (const float*)d_in[3];
    const float* W2 = (const float*)d_in[4];
    const float* b2 = (const float*)d_in[5];
    float* out = (float*)d_out;

    int N = in_sizes[0] / C_IN;     // 100000
    int E = in_sizes[1] / 2;        // 3200000
    int nblk = (N + SCAN_BLK - 1) / SCAN_BLK;   // 98

    k_detect <<<1, 1>>>((const int*)ei);
    k_zerodeg<<<(N + 255) / 256, 256>>>(N);
    k_hist   <<<(E + 255) / 256, 256>>>(ei, E);
    k_scanA  <<<nblk, SCAN_BLK>>>(N);
    k_scanB  <<<1, 128>>>(nblk);
    k_scanC  <<<(N + 255) / 256, 256>>>(N);
    k_gemm1  <<<(N * 32 + 255) / 256, 256>>>(x, W1, N);
    k_bucket <<<(E + 255) / 256, 256>>>(ei, E);
    k_agg1g2 <<<(N * 32 + 255) / 256, 256>>>(W2, b1, N);
    k_agg2fin<<<(N * 32 + 255) / 256, 256>>>(b2, out, N);
}